// round 8
// baseline (speedup 1.0000x reference)
#include <cuda_runtime.h>
#include <cstdint>
#include <cstddef>
#include <mma.h>
#include <math.h>

using namespace nvcuda;

// Problem constants
constexpr int B = 8, T = 4096, D = 768, H = 12, HD = 64, INTERVAL = 3;
constexpr int BT = B * T;                 // 32768 rows
constexpr float EPS = 1e-5f;

// Scratch (device globals: no allocation allowed in kernel_launch)
__device__ float g_q[(size_t)BT * D];
__device__ float g_k[(size_t)BT * D];
__device__ float g_v[(size_t)BT * D];
__device__ float g_attn[(size_t)BT * D];
__device__ float g_y[(size_t)BT * D];

// ---------------------------------------------------------------------------
// cp.async helpers
// ---------------------------------------------------------------------------
__device__ __forceinline__ void cp_async16(void* smem_dst, const void* gsrc) {
    uint32_t s = (uint32_t)__cvta_generic_to_shared(smem_dst);
    asm volatile("cp.async.cg.shared.global [%0], [%1], 16;\n" :: "r"(s), "l"(gsrc));
}
__device__ __forceinline__ void cp_async_commit() {
    asm volatile("cp.async.commit_group;\n");
}
template <int N>
__device__ __forceinline__ void cp_async_wait_group() {
    asm volatile("cp.async.wait_group %0;\n" :: "n"(N));
}

// ---------------------------------------------------------------------------
// TF32 wmma GEMM core: C[M,N] = A[M,K] @ W[K,N] + bias (+ residual)
// Block tile 128x128, BK=32, 2-stage cp.async pipeline in dynamic smem.
// 8 warps in a 4x2 grid; each warp computes a 32x64 tile (2x4 16x16 frags).
// M=32768, N=768, K=768 divide tiles exactly -> no bounds checks.
// One barrier per K-iteration; epilogue staged through reused smem.
// ---------------------------------------------------------------------------
#define BM 128
#define BN 128
#define BK 32
#define NSTAGE 2
#define APITCH (BK + 8)   // 40 floats = 160B rows (16B-aligned)
#define BPITCH (BN + 8)   // 136 floats = 544B rows (16B-aligned)
#define CPITCH 72         // epilogue chunk pitch (64+8)

// Per-stage float counts / offsets inside the dynamic smem pool.
#define A_ELEMS (BM * APITCH)              // 5120
#define B_ELEMS (BK * BPITCH)              // 4352
#define STAGE_ELEMS (A_ELEMS + B_ELEMS)    // 9472
// Dynamic smem: 2 stages = 75,776 B >= epilogue chunk (36,864 B).
#define SMEM_BYTES (NSTAGE * STAGE_ELEMS * 4)

__device__ __forceinline__ void gemm_body(
    const float* __restrict__ A, const float* __restrict__ W,
    const float* __restrict__ bias, const float* __restrict__ residual,
    float* __restrict__ C, int K, int N, int bm, int bn, float* smem)
{
    const int tid  = threadIdx.x;
    const int warp = tid >> 5;
    const int wm = (warp & 3) * 32;    // 4 warp rows of 32
    const int wn = (warp >> 2) * 64;   // 2 warp cols of 64

    // A tile: 128x32 = 1024 float4 chunks; B tile: 32x128 = 1024 float4 chunks.
    auto load_tiles = [&](int buf, int k0) {
        float* As = smem + buf * STAGE_ELEMS;
        float* Bs = As + A_ELEMS;
        #pragma unroll
        for (int i = 0; i < 4; i++) {
            int c = tid + i * 256;
            int r = c >> 3, c4 = (c & 7) * 4;
            cp_async16(&As[r * APITCH + c4], &A[(size_t)(bm + r) * K + k0 + c4]);
        }
        #pragma unroll
        for (int i = 0; i < 4; i++) {
            int c = tid + i * 256;
            int r = c >> 5, c4 = (c & 31) * 4;
            cp_async16(&Bs[r * BPITCH + c4], &W[(size_t)(k0 + r) * N + bn + c4]);
        }
        cp_async_commit();
    };

    wmma::fragment<wmma::accumulator, 16, 16, 8, float> acc[2][4];
    #pragma unroll
    for (int i = 0; i < 2; i++)
        #pragma unroll
        for (int j = 0; j < 4; j++)
            wmma::fill_fragment(acc[i][j], 0.0f);

    const int KT = K / BK;   // 24

    // Prime stage 0.
    load_tiles(0, 0);

    for (int kt = 0; kt < KT; kt++) {
        int cur = kt & 1;

        // At entry, the only outstanding cp.async group is tile kt
        // (tile kt+1 is committed below, AFTER this wait). Drain it, then
        // barrier so every warp sees all threads' fills — this same barrier
        // also protects buffer cur^1 (last read during iteration kt-1)
        // from the prefetch below.
        cp_async_wait_group<0>();
        __syncthreads();

        if (kt + 1 < KT) load_tiles(cur ^ 1, (kt + 1) * BK);

        const float* As = smem + cur * STAGE_ELEMS;
        const float* Bs = As + A_ELEMS;

        #pragma unroll
        for (int kk = 0; kk < BK; kk += 8) {
            wmma::fragment<wmma::matrix_a, 16, 16, 8, wmma::precision::tf32, wmma::row_major> a[2];
            wmma::fragment<wmma::matrix_b, 16, 16, 8, wmma::precision::tf32, wmma::row_major> b[4];
            #pragma unroll
            for (int i = 0; i < 2; i++) {
                wmma::load_matrix_sync(a[i], &As[(wm + i * 16) * APITCH + kk], APITCH);
                #pragma unroll
                for (int e = 0; e < a[i].num_elements; e++) a[i].x[e] = wmma::__float_to_tf32(a[i].x[e]);
            }
            #pragma unroll
            for (int j = 0; j < 4; j++) {
                wmma::load_matrix_sync(b[j], &Bs[kk * BPITCH + wn + j * 16], BPITCH);
                #pragma unroll
                for (int e = 0; e < b[j].num_elements; e++) b[j].x[e] = wmma::__float_to_tf32(b[j].x[e]);
            }
            #pragma unroll
            for (int i = 0; i < 2; i++)
                #pragma unroll
                for (int j = 0; j < 4; j++)
                    wmma::mma_sync(acc[i][j], a[i], b[j], acc[i][j]);
        }
        // No end-of-iteration barrier: the next iteration's entry barrier
        // (after wait_group) provides the needed ordering.
    }
    __syncthreads();   // all reads of As/Bs done before smem reuse as Cs

    // --- epilogue: two 128x64 chunks through smem, fused bias (+ residual) ---
    float (*Cs)[CPITCH] = (float (*)[CPITCH])smem;
    #pragma unroll
    for (int phase = 0; phase < 2; phase++) {
        if ((warp >> 2) == phase) {
            #pragma unroll
            for (int i = 0; i < 2; i++)
                #pragma unroll
                for (int j = 0; j < 4; j++)
                    wmma::store_matrix_sync(&Cs[wm + i * 16][j * 16], acc[i][j],
                                            CPITCH, wmma::mem_row_major);
        }
        __syncthreads();

        int ncol = bn + phase * 64;
        #pragma unroll
        for (int i = 0; i < 8; i++) {
            int idx = tid + i * 256;
            int r = idx >> 4, c4 = (idx & 15) * 4;
            size_t off = (size_t)(bm + r) * N + ncol + c4;
            float4 val = *(const float4*)&Cs[r][c4];
            float4 bi  = *(const float4*)&bias[ncol + c4];
            val.x += bi.x; val.y += bi.y; val.z += bi.z; val.w += bi.w;
            if (residual) {
                float4 res = *(const float4*)&residual[off];
                val.x += res.x; val.y += res.y; val.z += res.z; val.w += res.w;
            }
            *(float4*)&C[off] = val;
        }
        __syncthreads();
    }
}

// Fused Q/K/V projections: blockIdx.z selects the weight/bias/output set.
__global__ void __launch_bounds__(256) qkv_gemm(
    const float* __restrict__ x,
    const float* __restrict__ Wq, const float* __restrict__ Wk, const float* __restrict__ Wv,
    const float* __restrict__ bq, const float* __restrict__ bk, const float* __restrict__ bv)
{
    extern __shared__ __align__(16) float smem[];
    const float* W    = (blockIdx.z == 0) ? Wq : (blockIdx.z == 1) ? Wk : Wv;
    const float* bias = (blockIdx.z == 0) ? bq : (blockIdx.z == 1) ? bk : bv;
    float* C          = (blockIdx.z == 0) ? g_q : (blockIdx.z == 1) ? g_k : g_v;
    gemm_body(x, W, bias, nullptr, C, D, D, blockIdx.y * BM, blockIdx.x * BN, smem);
}

// O projection with residual add.
__global__ void __launch_bounds__(256) o_gemm(
    const float* __restrict__ Wo, const float* __restrict__ bo,
    const float* __restrict__ residual)
{
    extern __shared__ __align__(16) float smem[];
    gemm_body(g_attn, Wo, bo, residual, g_y, D, D, blockIdx.y * BM, blockIdx.x * BN, smem);
}

// ---------------------------------------------------------------------------
// Local 3-tap attention: one warp per (b, t, h). Heads are contiguous
// 64-float column slices of the [BT, D] Q/K/V, so no transpose/gather needed.
// ---------------------------------------------------------------------------
__global__ void __launch_bounds__(128) local_attn_kernel()
{
    int gwarp = (blockIdx.x * blockDim.x + threadIdx.x) >> 5;
    int lane = threadIdx.x & 31;
    if (gwarp >= B * T * H) return;

    int h = gwarp % H;
    int t = (gwarp / H) % T;
    int b = gwarp / (H * T);

    size_t rowbase = ((size_t)b * T + t) * D + h * HD;
    float2 q2 = *(const float2*)(g_q + rowbase + 2 * lane);

    float s[3];
    float2 v2[3];
    #pragma unroll
    for (int n = 0; n < 3; n++) {
        int tt = t + (n - 1) * INTERVAL;
        bool valid = (tt >= 0) && (tt < T);
        float dot = 0.0f;
        if (valid) {
            size_t kb = ((size_t)b * T + tt) * D + h * HD;
            float2 k2 = *(const float2*)(g_k + kb + 2 * lane);
            v2[n]     = *(const float2*)(g_v + kb + 2 * lane);
            dot = q2.x * k2.x + q2.y * k2.y;
        } else {
            v2[n] = make_float2(0.0f, 0.0f);
        }
        #pragma unroll
        for (int o = 16; o > 0; o >>= 1)
            dot += __shfl_xor_sync(0xffffffffu, dot, o);
        s[n] = valid ? dot * 0.125f : -INFINITY;   // 1/sqrt(64)
    }

    float m = fmaxf(s[0], fmaxf(s[1], s[2]));
    float w0 = __expf(s[0] - m);
    float w1 = __expf(s[1] - m);
    float w2 = __expf(s[2] - m);
    float inv = 1.0f / (w0 + w1 + w2);

    float2 o2;
    o2.x = (w0 * v2[0].x + w1 * v2[1].x + w2 * v2[2].x) * inv;
    o2.y = (w0 * v2[0].y + w1 * v2[1].y + w2 * v2[2].y) * inv;
    *(float2*)(g_attn + rowbase + 2 * lane) = o2;
}

// ---------------------------------------------------------------------------
// LayerNorm over D=768 per row; 192 threads/row, one float4 per thread.
// ---------------------------------------------------------------------------
__global__ void __launch_bounds__(192) layernorm_kernel(
    const float* __restrict__ gamma, const float* __restrict__ beta,
    float* __restrict__ out)
{
    int row = blockIdx.x;
    int c4 = threadIdx.x * 4;
    const float* y = g_y + (size_t)row * D;

    float4 v = *(const float4*)&y[c4];
    float sum   = v.x + v.y + v.z + v.w;
    float sumsq = v.x * v.x + v.y * v.y + v.z * v.z + v.w * v.w;

    #pragma unroll
    for (int o = 16; o > 0; o >>= 1) {
        sum   += __shfl_xor_sync(0xffffffffu, sum, o);
        sumsq += __shfl_xor_sync(0xffffffffu, sumsq, o);
    }
    __shared__ float ssum[6], ssq[6];
    int warp = threadIdx.x >> 5, lane = threadIdx.x & 31;
    if (lane == 0) { ssum[warp] = sum; ssq[warp] = sumsq; }
    __syncthreads();
    float tot = 0.0f, totsq = 0.0f;
    #pragma unroll
    for (int i = 0; i < 6; i++) { tot += ssum[i]; totsq += ssq[i]; }

    float mu   = tot * (1.0f / D);
    float var  = totsq * (1.0f / D) - mu * mu;
    float rstd = rsqrtf(var + EPS);

    float4 g = *(const float4*)&gamma[c4];
    float4 be = *(const float4*)&beta[c4];
    float4 o;
    o.x = (v.x - mu) * rstd * g.x + be.x;
    o.y = (v.y - mu) * rstd * g.y + be.y;
    o.z = (v.z - mu) * rstd * g.z + be.z;
    o.w = (v.w - mu) * rstd * g.w + be.w;
    *(float4*)&out[(size_t)row * D + c4] = o;
}

// ---------------------------------------------------------------------------
// Launch: x,Wq,bq,Wk,bk,Wv,bv,Wo,bo,gamma,beta in d_in[0..10] (metadata order)
// ---------------------------------------------------------------------------
extern "C" void kernel_launch(void* const* d_in, const int* in_sizes, int n_in,
                              void* d_out, int out_size)
{
    const float* x     = (const float*)d_in[0];
    const float* Wq    = (const float*)d_in[1];
    const float* bq    = (const float*)d_in[2];
    const float* Wk    = (const float*)d_in[3];
    const float* bk    = (const float*)d_in[4];
    const float* Wv    = (const float*)d_in[5];
    const float* bv    = (const float*)d_in[6];
    const float* Wo    = (const float*)d_in[7];
    const float* bo    = (const float*)d_in[8];
    const float* gamma = (const float*)d_in[9];
    const float* beta  = (const float*)d_in[10];
    float* out = (float*)d_out;

    // Opt in to >48KB dynamic smem (attribute set, not an allocation).
    cudaFuncSetAttribute(qkv_gemm, cudaFuncAttributeMaxDynamicSharedMemorySize, SMEM_BYTES);
    cudaFuncSetAttribute(o_gemm,   cudaFuncAttributeMaxDynamicSharedMemorySize, SMEM_BYTES);

    dim3 qkv_grid(D / BN, BT / BM, 3);   // (6, 256, 3)
    qkv_gemm<<<qkv_grid, 256, SMEM_BYTES>>>(x, Wq, Wk, Wv, bq, bk, bv);

    int nwarps = B * T * H;              // 393216
    local_attn_kernel<<<(nwarps * 32) / 128, 128>>>();

    dim3 o_grid(D / BN, BT / BM, 1);     // (6, 256)
    o_gemm<<<o_grid, 256, SMEM_BYTES>>>(Wo, bo, x);

    layernorm_kernel<<<BT, 192>>>(gamma, beta, out);
}

// round 12
// speedup vs baseline: 1.0491x; 1.0491x over previous
#include <cuda_runtime.h>
#include <cstdint>
#include <cstddef>
#include <mma.h>
#include <math.h>

using namespace nvcuda;

// Problem constants
constexpr int B = 8, T = 4096, D = 768, H = 12, HD = 64, INTERVAL = 3;
constexpr int BT = B * T;                 // 32768 rows
constexpr float EPS = 1e-5f;

// Scratch (device globals: no allocation allowed in kernel_launch)
__device__ float g_xr[(size_t)BT * D];     // x pre-rounded to tf32
__device__ float g_wr[(size_t)4 * D * D];  // Wq,Wk,Wv,Wo pre-rounded to tf32
__device__ float g_q[(size_t)BT * D];
__device__ float g_k[(size_t)BT * D];
__device__ float g_v[(size_t)BT * D];
__device__ float g_attn[(size_t)BT * D];   // attention out, tf32-rounded
__device__ float g_y[(size_t)BT * D];

// ---------------------------------------------------------------------------
// cp.async helpers
// ---------------------------------------------------------------------------
__device__ __forceinline__ void cp_async16(void* smem_dst, const void* gsrc) {
    uint32_t s = (uint32_t)__cvta_generic_to_shared(smem_dst);
    asm volatile("cp.async.cg.shared.global [%0], [%1], 16;\n" :: "r"(s), "l"(gsrc));
}
__device__ __forceinline__ void cp_async_commit() {
    asm volatile("cp.async.commit_group;\n");
}
template <int N>
__device__ __forceinline__ void cp_async_wait_group() {
    asm volatile("cp.async.wait_group %0;\n" :: "n"(N));
}

// ---------------------------------------------------------------------------
// TF32 wmma GEMM core: C[M,N] = A[M,K] @ W[K,N] + bias (+ residual)
// A and W are PRE-ROUNDED to tf32 -> no per-fragment conversion in mainloop.
// Block tile 128x128, BK=32, 2-stage cp.async pipeline in dynamic smem.
// 8 warps in a 4x2 grid; each warp computes a 32x64 tile (2x4 16x16 frags).
// M=32768, N=768, K=768 divide tiles exactly -> no bounds checks.
// One barrier per K-iteration; epilogue staged through reused smem.
// ---------------------------------------------------------------------------
#define BM 128
#define BN 128
#define BK 32
#define NSTAGE 2
#define APITCH (BK + 8)   // 40 floats = 160B rows (16B-aligned)
#define BPITCH (BN + 8)   // 136 floats = 544B rows (16B-aligned)
#define CPITCH 72         // epilogue chunk pitch (64+8)

// Per-stage float counts / offsets inside the dynamic smem pool.
#define A_ELEMS (BM * APITCH)              // 5120
#define B_ELEMS (BK * BPITCH)              // 4352
#define STAGE_ELEMS (A_ELEMS + B_ELEMS)    // 9472
// Dynamic smem: 2 stages = 75,776 B >= epilogue chunk (36,864 B).
#define SMEM_BYTES (NSTAGE * STAGE_ELEMS * 4)

__device__ __forceinline__ void gemm_body(
    const float* __restrict__ A, const float* __restrict__ W,
    const float* __restrict__ bias, const float* __restrict__ residual,
    float* __restrict__ C, int K, int N, int bm, int bn, float* smem)
{
    const int tid  = threadIdx.x;
    const int warp = tid >> 5;
    const int wm = (warp & 3) * 32;    // 4 warp rows of 32
    const int wn = (warp >> 2) * 64;   // 2 warp cols of 64

    // A tile: 128x32 = 1024 float4 chunks; B tile: 32x128 = 1024 float4 chunks.
    auto load_tiles = [&](int buf, int k0) {
        float* As = smem + buf * STAGE_ELEMS;
        float* Bs = As + A_ELEMS;
        #pragma unroll
        for (int i = 0; i < 4; i++) {
            int c = tid + i * 256;
            int r = c >> 3, c4 = (c & 7) * 4;
            cp_async16(&As[r * APITCH + c4], &A[(size_t)(bm + r) * K + k0 + c4]);
        }
        #pragma unroll
        for (int i = 0; i < 4; i++) {
            int c = tid + i * 256;
            int r = c >> 5, c4 = (c & 31) * 4;
            cp_async16(&Bs[r * BPITCH + c4], &W[(size_t)(k0 + r) * N + bn + c4]);
        }
        cp_async_commit();
    };

    wmma::fragment<wmma::accumulator, 16, 16, 8, float> acc[2][4];
    #pragma unroll
    for (int i = 0; i < 2; i++)
        #pragma unroll
        for (int j = 0; j < 4; j++)
            wmma::fill_fragment(acc[i][j], 0.0f);

    const int KT = K / BK;   // 24

    // Prime stage 0.
    load_tiles(0, 0);

    for (int kt = 0; kt < KT; kt++) {
        int cur = kt & 1;

        // At entry, the only outstanding cp.async group is tile kt
        // (tile kt+1 is committed below, AFTER this wait). Drain it, then
        // barrier so every warp sees all threads' fills — this same barrier
        // also protects buffer cur^1 (last read during iteration kt-1)
        // from the prefetch below.
        cp_async_wait_group<0>();
        __syncthreads();

        if (kt + 1 < KT) load_tiles(cur ^ 1, (kt + 1) * BK);

        const float* As = smem + cur * STAGE_ELEMS;
        const float* Bs = As + A_ELEMS;

        #pragma unroll
        for (int kk = 0; kk < BK; kk += 8) {
            wmma::fragment<wmma::matrix_a, 16, 16, 8, wmma::precision::tf32, wmma::row_major> a[2];
            wmma::fragment<wmma::matrix_b, 16, 16, 8, wmma::precision::tf32, wmma::row_major> b[4];
            // Data is pre-rounded to tf32 -> no __float_to_tf32 here.
            #pragma unroll
            for (int i = 0; i < 2; i++)
                wmma::load_matrix_sync(a[i], &As[(wm + i * 16) * APITCH + kk], APITCH);
            #pragma unroll
            for (int j = 0; j < 4; j++)
                wmma::load_matrix_sync(b[j], &Bs[kk * BPITCH + wn + j * 16], BPITCH);
            #pragma unroll
            for (int i = 0; i < 2; i++)
                #pragma unroll
                for (int j = 0; j < 4; j++)
                    wmma::mma_sync(acc[i][j], a[i], b[j], acc[i][j]);
        }
        // No end-of-iteration barrier: the next iteration's entry barrier
        // (after wait_group) provides the needed ordering.
    }
    __syncthreads();   // all reads of As/Bs done before smem reuse as Cs

    // --- epilogue: two 128x64 chunks through smem, fused bias (+ residual) ---
    // Active warps in `phase` have wn == phase*64, so the store column
    // wn - phase*64 + j*16 == j*16 lands in Cs[.][0..63] (same as R8).
    float (*Cs)[CPITCH] = (float (*)[CPITCH])smem;
    #pragma unroll
    for (int phase = 0; phase < 2; phase++) {
        if ((warp >> 2) == phase) {
            #pragma unroll
            for (int i = 0; i < 2; i++)
                #pragma unroll
                for (int j = 0; j < 4; j++)
                    wmma::store_matrix_sync(&Cs[wm + i * 16][wn - phase * 64 + j * 16], acc[i][j],
                                            CPITCH, wmma::mem_row_major);
        }
        __syncthreads();

        int ncol = bn + phase * 64;
        #pragma unroll
        for (int i = 0; i < 8; i++) {
            int idx = tid + i * 256;
            int r = idx >> 4, c4 = (idx & 15) * 4;
            size_t off = (size_t)(bm + r) * N + ncol + c4;
            float4 val = *(const float4*)&Cs[r][c4];
            float4 bi  = *(const float4*)&bias[ncol + c4];
            val.x += bi.x; val.y += bi.y; val.z += bi.z; val.w += bi.w;
            if (residual) {
                float4 res = *(const float4*)&residual[off];
                val.x += res.x; val.y += res.y; val.z += res.z; val.w += res.w;
            }
            *(float4*)&C[off] = val;
        }
        __syncthreads();
    }
}

// Fused Q/K/V projections: blockIdx.z selects the weight/bias/output set.
__global__ void __launch_bounds__(256) qkv_gemm(
    const float* __restrict__ bq, const float* __restrict__ bk, const float* __restrict__ bv)
{
    extern __shared__ __align__(16) float smem[];
    int z = blockIdx.z;
    const float* W    = g_wr + (size_t)z * D * D;
    const float* bias = (z == 0) ? bq : (z == 1) ? bk : bv;
    float* C          = (z == 0) ? g_q : (z == 1) ? g_k : g_v;
    gemm_body(g_xr, W, bias, nullptr, C, D, D, blockIdx.y * BM, blockIdx.x * BN, smem);
}

// O projection with residual add.
__global__ void __launch_bounds__(256) o_gemm(
    const float* __restrict__ bo, const float* __restrict__ residual)
{
    extern __shared__ __align__(16) float smem[];
    gemm_body(g_attn, g_wr + (size_t)3 * D * D, bo, residual, g_y, D, D,
              blockIdx.y * BM, blockIdx.x * BN, smem);
}

// ---------------------------------------------------------------------------
// Prep: round x and the four weight matrices to tf32 once per replay.
// ---------------------------------------------------------------------------
__global__ void __launch_bounds__(256) round_x_kernel(const float* __restrict__ x)
{
    size_t i4 = (size_t)(blockIdx.x * blockDim.x + threadIdx.x) * 4;
    float4 v = *(const float4*)&x[i4];
    v.x = wmma::__float_to_tf32(v.x);
    v.y = wmma::__float_to_tf32(v.y);
    v.z = wmma::__float_to_tf32(v.z);
    v.w = wmma::__float_to_tf32(v.w);
    *(float4*)&g_xr[i4] = v;
}

__global__ void __launch_bounds__(256) round_w_kernel(
    const float* __restrict__ Wq, const float* __restrict__ Wk,
    const float* __restrict__ Wv, const float* __restrict__ Wo)
{
    const float* W = (blockIdx.y == 0) ? Wq : (blockIdx.y == 1) ? Wk
                   : (blockIdx.y == 2) ? Wv : Wo;
    size_t i4 = (size_t)(blockIdx.x * blockDim.x + threadIdx.x) * 4;
    float4 v = *(const float4*)&W[i4];
    v.x = wmma::__float_to_tf32(v.x);
    v.y = wmma::__float_to_tf32(v.y);
    v.z = wmma::__float_to_tf32(v.z);
    v.w = wmma::__float_to_tf32(v.w);
    *(float4*)&g_wr[(size_t)blockIdx.y * D * D + i4] = v;
}

// ---------------------------------------------------------------------------
// Local 3-tap attention: one warp per (b, t, h). Heads are contiguous
// 64-float column slices of the [BT, D] Q/K/V. Output tf32-rounded for o_gemm.
// ---------------------------------------------------------------------------
__global__ void __launch_bounds__(128) local_attn_kernel()
{
    int gwarp = (blockIdx.x * blockDim.x + threadIdx.x) >> 5;
    int lane = threadIdx.x & 31;
    if (gwarp >= B * T * H) return;

    int h = gwarp % H;
    int t = (gwarp / H) % T;
    int b = gwarp / (H * T);

    size_t rowbase = ((size_t)b * T + t) * D + h * HD;
    float2 q2 = *(const float2*)(g_q + rowbase + 2 * lane);

    float s[3];
    float2 v2[3];
    #pragma unroll
    for (int n = 0; n < 3; n++) {
        int tt = t + (n - 1) * INTERVAL;
        bool valid = (tt >= 0) && (tt < T);
        float dot = 0.0f;
        if (valid) {
            size_t kb = ((size_t)b * T + tt) * D + h * HD;
            float2 k2 = *(const float2*)(g_k + kb + 2 * lane);
            v2[n]     = *(const float2*)(g_v + kb + 2 * lane);
            dot = q2.x * k2.x + q2.y * k2.y;
        } else {
            v2[n] = make_float2(0.0f, 0.0f);
        }
        #pragma unroll
        for (int o = 16; o > 0; o >>= 1)
            dot += __shfl_xor_sync(0xffffffffu, dot, o);
        s[n] = valid ? dot * 0.125f : -INFINITY;   // 1/sqrt(64)
    }

    float m = fmaxf(s[0], fmaxf(s[1], s[2]));
    float w0 = __expf(s[0] - m);
    float w1 = __expf(s[1] - m);
    float w2 = __expf(s[2] - m);
    float inv = 1.0f / (w0 + w1 + w2);

    float2 o2;
    o2.x = wmma::__float_to_tf32((w0 * v2[0].x + w1 * v2[1].x + w2 * v2[2].x) * inv);
    o2.y = wmma::__float_to_tf32((w0 * v2[0].y + w1 * v2[1].y + w2 * v2[2].y) * inv);
    *(float2*)(g_attn + rowbase + 2 * lane) = o2;
}

// ---------------------------------------------------------------------------
// LayerNorm over D=768 per row; 192 threads/row, one float4 per thread.
// ---------------------------------------------------------------------------
__global__ void __launch_bounds__(192) layernorm_kernel(
    const float* __restrict__ gamma, const float* __restrict__ beta,
    float* __restrict__ out)
{
    int row = blockIdx.x;
    int c4 = threadIdx.x * 4;
    const float* y = g_y + (size_t)row * D;

    float4 v = *(const float4*)&y[c4];
    float sum   = v.x + v.y + v.z + v.w;
    float sumsq = v.x * v.x + v.y * v.y + v.z * v.z + v.w * v.w;

    #pragma unroll
    for (int o = 16; o > 0; o >>= 1) {
        sum   += __shfl_xor_sync(0xffffffffu, sum, o);
        sumsq += __shfl_xor_sync(0xffffffffu, sumsq, o);
    }
    __shared__ float ssum[6], ssq[6];
    int warp = threadIdx.x >> 5, lane = threadIdx.x & 31;
    if (lane == 0) { ssum[warp] = sum; ssq[warp] = sumsq; }
    __syncthreads();
    float tot = 0.0f, totsq = 0.0f;
    #pragma unroll
    for (int i = 0; i < 6; i++) { tot += ssum[i]; totsq += ssq[i]; }

    float mu   = tot * (1.0f / D);
    float var  = totsq * (1.0f / D) - mu * mu;
    float rstd = rsqrtf(var + EPS);

    float4 g = *(const float4*)&gamma[c4];
    float4 be = *(const float4*)&beta[c4];
    float4 o;
    o.x = (v.x - mu) * rstd * g.x + be.x;
    o.y = (v.y - mu) * rstd * g.y + be.y;
    o.z = (v.z - mu) * rstd * g.z + be.z;
    o.w = (v.w - mu) * rstd * g.w + be.w;
    *(float4*)&out[(size_t)row * D + c4] = o;
}

// ---------------------------------------------------------------------------
// Launch: x,Wq,bq,Wk,bk,Wv,bv,Wo,bo,gamma,beta in d_in[0..10] (metadata order)
// ---------------------------------------------------------------------------
extern "C" void kernel_launch(void* const* d_in, const int* in_sizes, int n_in,
                              void* d_out, int out_size)
{
    const float* x     = (const float*)d_in[0];
    const float* Wq    = (const float*)d_in[1];
    const float* bq    = (const float*)d_in[2];
    const float* Wk    = (const float*)d_in[3];
    const float* bk    = (const float*)d_in[4];
    const float* Wv    = (const float*)d_in[5];
    const float* bv    = (const float*)d_in[6];
    const float* Wo    = (const float*)d_in[7];
    const float* bo    = (const float*)d_in[8];
    const float* gamma = (const float*)d_in[9];
    const float* beta  = (const float*)d_in[10];
    float* out = (float*)d_out;

    // Opt in to >48KB dynamic smem (attribute set, not an allocation).
    cudaFuncSetAttribute(qkv_gemm, cudaFuncAttributeMaxDynamicSharedMemorySize, SMEM_BYTES);
    cudaFuncSetAttribute(o_gemm,   cudaFuncAttributeMaxDynamicSharedMemorySize, SMEM_BYTES);

    // Prep: tf32 pre-rounding of x and weights.
    round_x_kernel<<<(BT * D / 4) / 256, 256>>>(x);
    round_w_kernel<<<dim3((D * D / 4) / 256, 4), 256>>>(Wq, Wk, Wv, Wo);

    dim3 qkv_grid(D / BN, BT / BM, 3);   // (6, 256, 3)
    qkv_gemm<<<qkv_grid, 256, SMEM_BYTES>>>(bq, bk, bv);

    int nwarps = B * T * H;              // 393216
    local_attn_kernel<<<(nwarps * 32) / 128, 128>>>();

    dim3 o_grid(D / BN, BT / BM, 1);     // (6, 256)
    o_gemm<<<o_grid, 256, SMEM_BYTES>>>(bo, x);

    layernorm_kernel<<<BT, 192>>>(gamma, beta, out);
}